// round 1
// baseline (speedup 1.0000x reference)
#include <cuda_runtime.h>
#include <math.h>

// C = tril(tril(A) @ tril(B)), N=4096, fp32.
// Block-triangular SIMT GEMM: 128x128 output tiles, BK=16, 256 threads,
// 8x8 register micro-tile per thread (split 4+4 layout for LDS.128).
// Masks applied at tile load => diagonal blocks correct, upper blocks zeroed.

#define BS 128
#define BK 16

__global__ __launch_bounds__(256, 2)
void trilmm_kernel(const float* __restrict__ A,
                   const float* __restrict__ B,
                   float* __restrict__ C,
                   int N)
{
    const int bj = blockIdx.x;   // column block
    const int bi = blockIdx.y;   // row block
    const int tid = threadIdx.x;

    // ---- strictly-upper blocks: write zeros (d_out is poisoned) ----
    if (bi < bj) {
        const int row0 = bi * BS;
        const int col0 = bj * BS;
        const float4 z = make_float4(0.f, 0.f, 0.f, 0.f);
        #pragma unroll
        for (int it = 0; it < 16; it++) {
            int lin = tid + it * 256;        // 0..4095 float4 slots
            int row = lin >> 5;              // /32
            int c4  = lin & 31;
            *reinterpret_cast<float4*>(&C[(size_t)(row0 + row) * N + col0 + c4 * 4]) = z;
        }
        return;
    }

    __shared__ float As[BK][BS];   // [k][m]  (A tile, transposed)
    __shared__ float Bs[BK][BS];   // [k][n]

    const int ty = tid >> 4;       // 0..15
    const int tx = tid & 15;       // 0..15

    float acc[8][8];
    #pragma unroll
    for (int i = 0; i < 8; i++)
        #pragma unroll
        for (int j = 0; j < 8; j++)
            acc[i][j] = 0.f;

    const int row0 = bi * BS;
    const int col0 = bj * BS;
    const int kBeg = bj * BS;                 // B[k,j] zero for k < j
    const int kEnd = (bi + 1) * BS;           // A[i,k] zero for k > i
    // (both clamped to N implicitly since bi,bj < N/BS)

    // A-load indexing: 128 rows x 4 float4s per row -> 512 float4s, 2/thread
    const int aRow0 = tid >> 2;          // iter 0: rows 0..63
    const int aC4_0 = tid & 3;
    // B-load indexing: 16 rows x 32 float4s per row -> 512 float4s, 2/thread
    const int bRow0 = tid >> 5;          // iter 0: rows 0..7
    const int bC4_0 = tid & 31;

    for (int k0 = kBeg; k0 < kEnd; k0 += BK) {

        // ---- load A tile (masked: k <= i), store transposed ----
        #pragma unroll
        for (int it = 0; it < 2; it++) {
            int row = aRow0 + it * 64;
            int c4  = aC4_0;
            int gRow = row0 + row;
            int gK   = k0 + c4 * 4;
            float4 v = *reinterpret_cast<const float4*>(&A[(size_t)gRow * N + gK]);
            // mask: element k = gK+e valid iff gK+e <= gRow
            if (gK + 0 > gRow) v.x = 0.f;
            if (gK + 1 > gRow) v.y = 0.f;
            if (gK + 2 > gRow) v.z = 0.f;
            if (gK + 3 > gRow) v.w = 0.f;
            As[c4 * 4 + 0][row] = v.x;
            As[c4 * 4 + 1][row] = v.y;
            As[c4 * 4 + 2][row] = v.z;
            As[c4 * 4 + 3][row] = v.w;
        }

        // ---- load B tile (masked: j <= k) ----
        #pragma unroll
        for (int it = 0; it < 2; it++) {
            int krow = bRow0 + it * 8;
            int c4   = bC4_0;
            int gK   = k0 + krow;
            int gCol = col0 + c4 * 4;
            float4 v = *reinterpret_cast<const float4*>(&B[(size_t)gK * N + gCol]);
            if (gCol + 0 > gK) v.x = 0.f;
            if (gCol + 1 > gK) v.y = 0.f;
            if (gCol + 2 > gK) v.z = 0.f;
            if (gCol + 3 > gK) v.w = 0.f;
            *reinterpret_cast<float4*>(&Bs[krow][c4 * 4]) = v;
        }

        __syncthreads();

        // ---- FMA mainloop ----
        #pragma unroll
        for (int kk = 0; kk < BK; kk++) {
            float4 a0 = *reinterpret_cast<const float4*>(&As[kk][ty * 4]);
            float4 a1 = *reinterpret_cast<const float4*>(&As[kk][64 + ty * 4]);
            float4 b0 = *reinterpret_cast<const float4*>(&Bs[kk][tx * 4]);
            float4 b1 = *reinterpret_cast<const float4*>(&Bs[kk][64 + tx * 4]);

            float ra[8] = {a0.x, a0.y, a0.z, a0.w, a1.x, a1.y, a1.z, a1.w};
            float rb[8] = {b0.x, b0.y, b0.z, b0.w, b1.x, b1.y, b1.z, b1.w};

            #pragma unroll
            for (int i = 0; i < 8; i++)
                #pragma unroll
                for (int j = 0; j < 8; j++)
                    acc[i][j] = fmaf(ra[i], rb[j], acc[i][j]);
        }

        __syncthreads();
    }

    // ---- epilogue: rows {ty*4+a, 64+ty*4+a}, cols {tx*4+b, 64+tx*4+b} ----
    #pragma unroll
    for (int ih = 0; ih < 2; ih++) {
        #pragma unroll
        for (int a = 0; a < 4; a++) {
            int r = row0 + ih * 64 + ty * 4 + a;
            int i = ih * 4 + a;
            float4 v0 = make_float4(acc[i][0], acc[i][1], acc[i][2], acc[i][3]);
            float4 v1 = make_float4(acc[i][4], acc[i][5], acc[i][6], acc[i][7]);
            *reinterpret_cast<float4*>(&C[(size_t)r * N + col0 + tx * 4])      = v0;
            *reinterpret_cast<float4*>(&C[(size_t)r * N + col0 + 64 + tx * 4]) = v1;
        }
    }
}

extern "C" void kernel_launch(void* const* d_in, const int* in_sizes, int n_in,
                              void* d_out, int out_size)
{
    const float* A = (const float*)d_in[0];
    const float* B = (const float*)d_in[1];
    float* C = (float*)d_out;

    // N*N elements per input matrix
    int N = 1;
    {
        long long total = in_sizes[0];
        int lo = 1, hi = 65536;
        while (lo < hi) {                 // integer sqrt
            int mid = (lo + hi) >> 1;
            if ((long long)mid * mid < total) lo = mid + 1; else hi = mid;
        }
        N = lo;
    }

    dim3 grid(N / BS, N / BS);
    trilmm_kernel<<<grid, 256>>>(A, B, C, N);
}

// round 5
// speedup vs baseline: 2.9242x; 2.9242x over previous
#include <cuda_runtime.h>
#include <cuda_bf16.h>
#include <stdint.h>

// C = tril(tril(A) @ tril(B)), N=4096 fp32.
// bf16-split (3-pass) GEMM on mma.sync.m16n8k16 (HMMA path, no sm_103a-only PTX).
// Block-triangular: only lower blocks computed; K range per block limited.

#define BS 128
#define BK 32
#define APAD 40    // A smem row stride (bf16): 32 + 8 pad
#define BPAD 136   // B smem row stride (bf16): 128 + 8 pad

__device__ __forceinline__ uint32_t smem_u32(const void* p) {
    uint32_t a;
    asm("{ .reg .u64 t; cvta.to.shared.u64 t, %1; cvt.u32.u64 %0, t; }"
        : "=r"(a) : "l"(p));
    return a;
}
__device__ __forceinline__ uint32_t pack2(float a, float b) {
    __nv_bfloat162 v = __floats2bfloat162_rn(a, b);
    return *reinterpret_cast<uint32_t*>(&v);
}
__device__ __forceinline__ void splitf(float x, float& h, float& l) {
    __nv_bfloat16 bh = __float2bfloat16(x);
    h = __bfloat162float(bh);
    l = x - h;
}
__device__ __forceinline__ void ldsm4(uint32_t* r, uint32_t addr) {
    asm volatile("ldmatrix.sync.aligned.m8n8.x4.shared.b16 {%0,%1,%2,%3}, [%4];"
                 : "=r"(r[0]), "=r"(r[1]), "=r"(r[2]), "=r"(r[3]) : "r"(addr));
}
__device__ __forceinline__ void ldsm4t(uint32_t* r, uint32_t addr) {
    asm volatile("ldmatrix.sync.aligned.m8n8.x4.trans.shared.b16 {%0,%1,%2,%3}, [%4];"
                 : "=r"(r[0]), "=r"(r[1]), "=r"(r[2]), "=r"(r[3]) : "r"(addr));
}
__device__ __forceinline__ void mma16816(float* c, const uint32_t* a, const uint32_t* b) {
    asm volatile(
        "mma.sync.aligned.m16n8k16.row.col.f32.bf16.bf16.f32 "
        "{%0,%1,%2,%3}, {%4,%5,%6,%7}, {%8,%9}, {%0,%1,%2,%3};"
        : "+f"(c[0]), "+f"(c[1]), "+f"(c[2]), "+f"(c[3])
        : "r"(a[0]), "r"(a[1]), "r"(a[2]), "r"(a[3]), "r"(b[0]), "r"(b[1]));
}

__global__ __launch_bounds__(256, 2)
void trilmm_mma_kernel(const float* __restrict__ A,
                       const float* __restrict__ B,
                       float* __restrict__ C,
                       int N, int nb)
{
    const int tid = threadIdx.x;
    const int lowerCnt = nb * (nb + 1) / 2;
    const int bid = blockIdx.x;

    // ---------- zero-fill CTAs (strictly upper blocks) ----------
    if (bid >= lowerCnt) {
        int t = bid - lowerCnt;
        int bi = 0, bj = 0;
        for (int d = 1; d < nb; d++) {
            int cnt = nb - d;
            if (t < cnt) { bi = t; bj = t + d; break; }
            t -= cnt;
        }
        const int row0 = bi * BS, col0 = bj * BS;
        const float4 z = make_float4(0.f, 0.f, 0.f, 0.f);
        #pragma unroll
        for (int it = 0; it < 16; it++) {
            int lin = tid + it * 256;
            int r = lin >> 5, c4 = lin & 31;
            *reinterpret_cast<float4*>(&C[(size_t)(row0 + r) * N + col0 + c4 * 4]) = z;
        }
        return;
    }

    // ---------- map bid -> (bi,bj), largest-work CTAs first ----------
    int bi, bj;
    {
        int t = bid, dd = nb - 1;
        for (; dd >= 0; dd--) {
            int cnt = nb - dd;
            if (t < cnt) break;
            t -= cnt;
        }
        bj = t; bi = dd + t;
    }

    __shared__ __align__(16) __nv_bfloat16 sAhi[BS * APAD];
    __shared__ __align__(16) __nv_bfloat16 sAlo[BS * APAD];
    __shared__ __align__(16) __nv_bfloat16 sBhi[BK * BPAD];
    __shared__ __align__(16) __nv_bfloat16 sBlo[BK * BPAD];

    const int lane = tid & 31;
    const int wid  = tid >> 5;
    const int wm   = wid >> 2;     // 0..1  (64 rows each)
    const int wn   = wid & 3;      // 0..3  (32 cols each)

    const int row0 = bi * BS, col0 = bj * BS;
    const int kBeg = bj * BS;
    const int nchunk = (bi - bj + 1) * (BS / BK);

    float acc[4][4][4];
    #pragma unroll
    for (int i = 0; i < 4; i++)
        #pragma unroll
        for (int j = 0; j < 4; j++)
            #pragma unroll
            for (int e = 0; e < 4; e++)
                acc[i][j][e] = 0.f;

    const uint32_t aHiB = smem_u32(sAhi), aLoB = smem_u32(sAlo);
    const uint32_t bHiB = smem_u32(sBhi), bLoB = smem_u32(sBlo);

    // ldmatrix per-lane byte offsets (constant across chunks; + ks term inside)
    uint32_t a_off[4];
    #pragma unroll
    for (int mt = 0; mt < 4; mt++)
        a_off[mt] = (uint32_t)(((wm * 64 + mt * 16 + (lane & 15)) * APAD
                                + (lane >> 4) * 8) * 2);
    uint32_t b_off[2];
    #pragma unroll
    for (int p = 0; p < 2; p++)
        b_off[p] = (uint32_t)(((lane & 15) * BPAD
                               + wn * 32 + p * 16 + (lane >> 4) * 8) * 2);

    // convert-stage indexing
    const int aRow = tid >> 1, aHalf = (tid & 1) * 16;
    const int bK = tid >> 3, bN0 = (tid & 7) * 16;

    for (int c = 0; c < nchunk; c++) {
        const int k0 = kBeg + c * BK;

        // ---- A tile: 128 x 32 fp32 -> masked hi/lo bf16 [m][k] ----
        {
            const int gRow = row0 + aRow;
            const float* gA = &A[(size_t)gRow * N + k0 + aHalf];
            uint32_t* dh = (uint32_t*)sAhi + ((aRow * APAD + aHalf) >> 1);
            uint32_t* dl = (uint32_t*)sAlo + ((aRow * APAD + aHalf) >> 1);
            #pragma unroll
            for (int f = 0; f < 4; f++) {
                float4 v = *reinterpret_cast<const float4*>(&gA[f * 4]);
                const int gk = k0 + aHalf + f * 4;
                if (gk + 0 > gRow) v.x = 0.f;
                if (gk + 1 > gRow) v.y = 0.f;
                if (gk + 2 > gRow) v.z = 0.f;
                if (gk + 3 > gRow) v.w = 0.f;
                float hx, lx, hy, ly, hz, lz, hw, lw;
                splitf(v.x, hx, lx); splitf(v.y, hy, ly);
                splitf(v.z, hz, lz); splitf(v.w, hw, lw);
                dh[f * 2 + 0] = pack2(hx, hy);
                dh[f * 2 + 1] = pack2(hz, hw);
                dl[f * 2 + 0] = pack2(lx, ly);
                dl[f * 2 + 1] = pack2(lz, lw);
            }
        }

        // ---- B tile: 32 x 128 fp32 -> masked hi/lo bf16 [k][n] ----
        {
            const int gK = k0 + bK;
            const float* gB = &B[(size_t)gK * N + col0 + bN0];
            uint32_t* dh = (uint32_t*)sBhi + ((bK * BPAD + bN0) >> 1);
            uint32_t* dl = (uint32_t*)sBlo + ((bK * BPAD + bN0) >> 1);
            #pragma unroll
            for (int f = 0; f < 4; f++) {
                float4 v = *reinterpret_cast<const float4*>(&gB[f * 4]);
                const int gn = col0 + bN0 + f * 4;
                if (gn + 0 > gK) v.x = 0.f;
                if (gn + 1 > gK) v.y = 0.f;
                if (gn + 2 > gK) v.z = 0.f;
                if (gn + 3 > gK) v.w = 0.f;
                float hx, lx, hy, ly, hz, lz, hw, lw;
                splitf(v.x, hx, lx); splitf(v.y, hy, ly);
                splitf(v.z, hz, lz); splitf(v.w, hw, lw);
                dh[f * 2 + 0] = pack2(hx, hy);
                dh[f * 2 + 1] = pack2(hz, hw);
                dl[f * 2 + 0] = pack2(lx, ly);
                dl[f * 2 + 1] = pack2(lz, lw);
            }
        }

        __syncthreads();

        // ---- MMA: 2 k-steps of 16, 3 split passes each ----
        #pragma unroll
        for (int ks = 0; ks < 2; ks++) {
            uint32_t af[4][4], bh[2][4], bl[2][4];
            #pragma unroll
            for (int mt = 0; mt < 4; mt++)
                ldsm4(af[mt], aHiB + a_off[mt] + ks * 32);
            #pragma unroll
            for (int p = 0; p < 2; p++) {
                ldsm4t(bh[p], bHiB + b_off[p] + ks * (16 * BPAD * 2));
                ldsm4t(bl[p], bLoB + b_off[p] + ks * (16 * BPAD * 2));
            }
            // pass 1: Ahi x Bhi
            #pragma unroll
            for (int mt = 0; mt < 4; mt++)
                #pragma unroll
                for (int nt = 0; nt < 4; nt++)
                    mma16816(acc[mt][nt], af[mt], &bh[nt >> 1][(nt & 1) * 2]);
            // pass 2: Ahi x Blo
            #pragma unroll
            for (int mt = 0; mt < 4; mt++)
                #pragma unroll
                for (int nt = 0; nt < 4; nt++)
                    mma16816(acc[mt][nt], af[mt], &bl[nt >> 1][(nt & 1) * 2]);
            // pass 3: Alo x Bhi (reuse af regs)
            #pragma unroll
            for (int mt = 0; mt < 4; mt++)
                ldsm4(af[mt], aLoB + a_off[mt] + ks * 32);
            #pragma unroll
            for (int mt = 0; mt < 4; mt++)
                #pragma unroll
                for (int nt = 0; nt < 4; nt++)
                    mma16816(acc[mt][nt], af[mt], &bh[nt >> 1][(nt & 1) * 2]);
        }

        __syncthreads();
    }

    // ---- epilogue: direct stores from acc fragments ----
    #pragma unroll
    for (int mt = 0; mt < 4; mt++) {
        #pragma unroll
        for (int nt = 0; nt < 4; nt++) {
            const int r  = row0 + wm * 64 + mt * 16 + (lane >> 2);
            const int cb = col0 + wn * 32 + nt * 8 + (lane & 3) * 2;
            float2 v0 = make_float2(acc[mt][nt][0], acc[mt][nt][1]);
            float2 v1 = make_float2(acc[mt][nt][2], acc[mt][nt][3]);
            *reinterpret_cast<float2*>(&C[(size_t)r * N + cb])       = v0;
            *reinterpret_cast<float2*>(&C[(size_t)(r + 8) * N + cb]) = v1;
        }
    }
}

extern "C" void kernel_launch(void* const* d_in, const int* in_sizes, int n_in,
                              void* d_out, int out_size)
{
    const float* A = (const float*)d_in[0];
    const float* B = (const float*)d_in[1];
    float* C = (float*)d_out;

    int N = 1;
    {
        long long total = in_sizes[0];
        int lo = 1, hi = 65536;
        while (lo < hi) {
            int mid = (lo + hi) >> 1;
            if ((long long)mid * mid < total) lo = mid + 1; else hi = mid;
        }
        N = lo;
    }
    const int nb = N / BS;

    trilmm_mma_kernel<<<nb * nb, 256>>>(A, B, C, N, nb);
}

// round 8
// speedup vs baseline: 3.3544x; 1.1471x over previous
#include <cuda_runtime.h>
#include <cuda_bf16.h>
#include <stdint.h>

// C = tril(tril(A) @ tril(B)), N=4096 fp32.
// Prepass splits A,B into tril-masked bf16 hi/lo planes (device scratch);
// main kernel is a cp.async double-buffered block-triangular GEMM on
// mma.sync.m16n8k16 (3-pass bf16 split accumulation).

#define BS 128
#define BK 32
#define APAD 40     // bf16 elems per A smem row (32 + 8 pad), 80B stride
#define BPAD 136    // bf16 elems per B smem row (128 + 8 pad), 272B stride

#define AHI_OFF 0
#define ALO_OFF (128 * APAD * 2)                 // 10240
#define BHI_OFF (ALO_OFF * 2)                    // 20480
#define BLO_OFF (BHI_OFF + BK * BPAD * 2)        // 29184
#define STAGE_BYTES (BLO_OFF + BK * BPAD * 2)    // 37888
#define NSTAGE 2

#define NMAX 4096ULL
__device__ __align__(16) __nv_bfloat16 gAhi[NMAX * NMAX];
__device__ __align__(16) __nv_bfloat16 gAlo[NMAX * NMAX];
__device__ __align__(16) __nv_bfloat16 gBhi[NMAX * NMAX];
__device__ __align__(16) __nv_bfloat16 gBlo[NMAX * NMAX];

// ---------------- helpers ----------------
__device__ __forceinline__ uint32_t smem_u32(const void* p) {
    uint32_t a;
    asm("{ .reg .u64 t; cvta.to.shared.u64 t, %1; cvt.u32.u64 %0, t; }"
        : "=r"(a) : "l"(p));
    return a;
}
__device__ __forceinline__ uint32_t pack2(float a, float b) {
    __nv_bfloat162 v = __floats2bfloat162_rn(a, b);
    return *reinterpret_cast<uint32_t*>(&v);
}
__device__ __forceinline__ void splitf(float x, float& h, float& l) {
    __nv_bfloat16 bh = __float2bfloat16(x);
    h = __bfloat162float(bh);
    l = x - h;
}
__device__ __forceinline__ void ldsm4(uint32_t* r, uint32_t addr) {
    asm volatile("ldmatrix.sync.aligned.m8n8.x4.shared.b16 {%0,%1,%2,%3}, [%4];"
                 : "=r"(r[0]), "=r"(r[1]), "=r"(r[2]), "=r"(r[3]) : "r"(addr));
}
__device__ __forceinline__ void ldsm4t(uint32_t* r, uint32_t addr) {
    asm volatile("ldmatrix.sync.aligned.m8n8.x4.trans.shared.b16 {%0,%1,%2,%3}, [%4];"
                 : "=r"(r[0]), "=r"(r[1]), "=r"(r[2]), "=r"(r[3]) : "r"(addr));
}
__device__ __forceinline__ void mma16816(float* c, const uint32_t* a, const uint32_t* b) {
    asm volatile(
        "mma.sync.aligned.m16n8k16.row.col.f32.bf16.bf16.f32 "
        "{%0,%1,%2,%3}, {%4,%5,%6,%7}, {%8,%9}, {%0,%1,%2,%3};"
        : "+f"(c[0]), "+f"(c[1]), "+f"(c[2]), "+f"(c[3])
        : "r"(a[0]), "r"(a[1]), "r"(a[2]), "r"(a[3]), "r"(b[0]), "r"(b[1]));
}
__device__ __forceinline__ void cp16(uint32_t dst, const void* src) {
    asm volatile("cp.async.cg.shared.global [%0], [%1], 16;"
                 :: "r"(dst), "l"(__cvta_generic_to_global(src)) : "memory");
}
__device__ __forceinline__ void cp_commit() {
    asm volatile("cp.async.commit_group;" ::: "memory");
}
template<int n> __device__ __forceinline__ void cp_wait() {
    asm volatile("cp.async.wait_group %0;" :: "n"(n) : "memory");
}

// ---------------- prepass: fp32 -> tril-masked bf16 hi/lo ----------------
__global__ __launch_bounds__(256)
void split_prepass(const float* __restrict__ A, const float* __restrict__ B, int N)
{
    size_t per = (size_t)N * N / 8;
    size_t id = (size_t)blockIdx.x * 256 + threadIdx.x;
    if (id >= 2 * per) return;
    const bool isA = id < per;
    size_t e = (isA ? id : id - per) * 8;
    const int row = (int)(e / (size_t)N);
    const int col = (int)(e % (size_t)N);

    const float* S = isA ? A : B;
    __nv_bfloat16* dh = isA ? gAhi : gBhi;
    __nv_bfloat16* dl = isA ? gAlo : gBlo;

    float4 v0 = *reinterpret_cast<const float4*>(S + e);
    float4 v1 = *reinterpret_cast<const float4*>(S + e + 4);
    float f[8] = {v0.x, v0.y, v0.z, v0.w, v1.x, v1.y, v1.z, v1.w};

    uint32_t hp[4], lp[4];
    #pragma unroll
    for (int j = 0; j < 8; j += 2) {
        // tril mask for both A(i,k): k<=i and B(k,n): n<=k  =>  col <= row
        float x0 = (col + j     > row) ? 0.f : f[j];
        float x1 = (col + j + 1 > row) ? 0.f : f[j + 1];
        float h0, l0, h1, l1;
        splitf(x0, h0, l0);
        splitf(x1, h1, l1);
        hp[j >> 1] = pack2(h0, h1);
        lp[j >> 1] = pack2(l0, l1);
    }
    *reinterpret_cast<uint4*>(dh + e) = make_uint4(hp[0], hp[1], hp[2], hp[3]);
    *reinterpret_cast<uint4*>(dl + e) = make_uint4(lp[0], lp[1], lp[2], lp[3]);
}

// ---------------- main GEMM ----------------
__global__ __launch_bounds__(256, 2)
void trilmm_mma_kernel(float* __restrict__ C, int N, int nb)
{
    extern __shared__ char smem[];
    const int tid = threadIdx.x;
    const int lowerCnt = nb * (nb + 1) / 2;
    const int bid = blockIdx.x;

    // ---------- zero-fill CTAs (strictly upper blocks) ----------
    if (bid >= lowerCnt) {
        int t = bid - lowerCnt;
        int bi = 0, bj = 0;
        for (int d = 1; d < nb; d++) {
            int cnt = nb - d;
            if (t < cnt) { bi = t; bj = t + d; break; }
            t -= cnt;
        }
        const int row0 = bi * BS, col0 = bj * BS;
        const float4 z = make_float4(0.f, 0.f, 0.f, 0.f);
        #pragma unroll
        for (int it = 0; it < 16; it++) {
            int lin = tid + it * 256;
            int r = lin >> 5, c4 = lin & 31;
            *reinterpret_cast<float4*>(&C[(size_t)(row0 + r) * N + col0 + c4 * 4]) = z;
        }
        return;
    }

    // ---------- map bid -> (bi,bj), largest-work CTAs first ----------
    int bi, bj;
    {
        int t = bid, dd = nb - 1;
        for (; dd >= 0; dd--) {
            int cnt = nb - dd;
            if (t < cnt) break;
            t -= cnt;
        }
        bj = t; bi = dd + t;
    }

    const int lane = tid & 31;
    const int wid  = tid >> 5;
    const int wm   = wid >> 2;     // 0..1
    const int wn   = wid & 3;      // 0..3

    const int row0 = bi * BS, col0 = bj * BS;
    const int kBeg = bj * BS;
    const int nchunk = (bi - bj + 1) * (BS / BK);

    const uint32_t sb = smem_u32(smem);

    float acc[4][4][4];
    #pragma unroll
    for (int i = 0; i < 4; i++)
        #pragma unroll
        for (int j = 0; j < 4; j++)
            #pragma unroll
            for (int e = 0; e < 4; e++)
                acc[i][j][e] = 0.f;

    // ldmatrix per-lane byte offsets within a stage
    uint32_t a_off[4];
    #pragma unroll
    for (int mt = 0; mt < 4; mt++)
        a_off[mt] = (uint32_t)(((wm * 64 + mt * 16 + (lane & 15)) * APAD
                                + (lane >> 4) * 8) * 2);
    uint32_t b_off[2];
    #pragma unroll
    for (int p = 0; p < 2; p++)
        b_off[p] = (uint32_t)(((lane & 15) * BPAD
                               + wn * 32 + p * 16 + (lane >> 4) * 8) * 2);

    // cp.async indexing (per thread, 8 x 16B per stage)
    const int aRow = tid >> 2, aSeg = (tid & 3) * 8;   // A: 128 rows x 4 segs of 8 bf16
    const int bRow = tid >> 4, bSeg = (tid & 15) * 8;  // B: 32 rows x 16 segs, 2 iters

    auto issue = [&](int c) {
        const uint32_t base = sb + (uint32_t)(c % NSTAGE) * STAGE_BYTES;
        const int k0 = kBeg + c * BK;
        // A hi/lo: rows aRow, aRow+64
        #pragma unroll
        for (int i = 0; i < 2; i++) {
            const int r = aRow + i * 64;
            const size_t g = (size_t)(row0 + r) * N + k0 + aSeg;
            const uint32_t d = base + AHI_OFF + (uint32_t)((r * APAD + aSeg) * 2);
            cp16(d, gAhi + g);
            cp16(d + (ALO_OFF - AHI_OFF), gAlo + g);
        }
        // B hi/lo: rows bRow, bRow+16
        #pragma unroll
        for (int i = 0; i < 2; i++) {
            const int r = bRow + i * 16;
            const size_t g = (size_t)(k0 + r) * N + col0 + bSeg;
            const uint32_t d = base + BHI_OFF + (uint32_t)((r * BPAD + bSeg) * 2);
            cp16(d, gBhi + g);
            cp16(d + (BLO_OFF - BHI_OFF), gBlo + g);
        }
        cp_commit();
    };

    issue(0);

    for (int c = 0; c < nchunk; c++) {
        // prefetch next chunk into the other buffer (overlaps with MMA below)
        if (c + 1 < nchunk) {
            issue(c + 1);
            cp_wait<1>();          // stage c complete
        } else {
            cp_wait<0>();
        }
        __syncthreads();

        const uint32_t stB = sb + (uint32_t)(c % NSTAGE) * STAGE_BYTES;
        const uint32_t aHiB = stB + AHI_OFF, aLoB = stB + ALO_OFF;
        const uint32_t bHiB = stB + BHI_OFF, bLoB = stB + BLO_OFF;

        #pragma unroll
        for (int ks = 0; ks < 2; ks++) {
            uint32_t af[4][4], bh[2][4], bl[2][4];
            #pragma unroll
            for (int mt = 0; mt < 4; mt++)
                ldsm4(af[mt], aHiB + a_off[mt] + ks * 32);
            #pragma unroll
            for (int p = 0; p < 2; p++) {
                ldsm4t(bh[p], bHiB + b_off[p] + ks * (16 * BPAD * 2));
                ldsm4t(bl[p], bLoB + b_off[p] + ks * (16 * BPAD * 2));
            }
            // pass 1: Ahi x Bhi
            #pragma unroll
            for (int mt = 0; mt < 4; mt++)
                #pragma unroll
                for (int nt = 0; nt < 4; nt++)
                    mma16816(acc[mt][nt], af[mt], &bh[nt >> 1][(nt & 1) * 2]);
            // pass 2: Ahi x Blo
            #pragma unroll
            for (int mt = 0; mt < 4; mt++)
                #pragma unroll
                for (int nt = 0; nt < 4; nt++)
                    mma16816(acc[mt][nt], af[mt], &bl[nt >> 1][(nt & 1) * 2]);
            // pass 3: Alo x Bhi (reuse af regs)
            #pragma unroll
            for (int mt = 0; mt < 4; mt++)
                ldsm4(af[mt], aLoB + a_off[mt] + ks * 32);
            #pragma unroll
            for (int mt = 0; mt < 4; mt++)
                #pragma unroll
                for (int nt = 0; nt < 4; nt++)
                    mma16816(acc[mt][nt], af[mt], &bh[nt >> 1][(nt & 1) * 2]);
        }

        __syncthreads();
    }

    // ---- epilogue: direct stores from acc fragments ----
    #pragma unroll
    for (int mt = 0; mt < 4; mt++) {
        #pragma unroll
        for (int nt = 0; nt < 4; nt++) {
            const int r  = row0 + wm * 64 + mt * 16 + (lane >> 2);
            const int cb = col0 + wn * 32 + nt * 8 + (lane & 3) * 2;
            float2 v0 = make_float2(acc[mt][nt][0], acc[mt][nt][1]);
            float2 v1 = make_float2(acc[mt][nt][2], acc[mt][nt][3]);
            *reinterpret_cast<float2*>(&C[(size_t)r * N + cb])       = v0;
            *reinterpret_cast<float2*>(&C[(size_t)(r + 8) * N + cb]) = v1;
        }
    }
}

// ---------------- launch ----------------
extern "C" void kernel_launch(void* const* d_in, const int* in_sizes, int n_in,
                              void* d_out, int out_size)
{
    const float* A = (const float*)d_in[0];
    const float* B = (const float*)d_in[1];
    float* C = (float*)d_out;

    int N = 1;
    {
        long long total = in_sizes[0];
        int lo = 1, hi = 65536;
        while (lo < hi) {
            int mid = (lo + hi) >> 1;
            if ((long long)mid * mid < total) lo = mid + 1; else hi = mid;
        }
        N = lo;
    }
    const int nb = N / BS;

    // prepass: one thread per 8 elements, A and B together
    {
        long long groups = 2LL * N * N / 8;
        int blocks = (int)((groups + 255) / 256);
        split_prepass<<<blocks, 256>>>(A, B, N);
    }

    // unconditional (idempotent, no static guard, capture-safe: no stream work)
    cudaFuncSetAttribute(trilmm_mma_kernel,
                         cudaFuncAttributeMaxDynamicSharedMemorySize,
                         STAGE_BYTES * NSTAGE);
    trilmm_mma_kernel<<<nb * nb, 256, STAGE_BYTES * NSTAGE>>>(C, N, nb);
}

// round 9
// speedup vs baseline: 3.5407x; 1.0555x over previous
#include <cuda_runtime.h>
#include <cuda_bf16.h>
#include <stdint.h>

// C = tril(tril(A) @ tril(B)), N=4096 fp32.
// R9: prepass -> bf16 hi/lo planes; zero-fill C; split-K balanced main GEMM
// (cp.async double-buffered mma.sync m16n8k16, 3-pass bf16 split), multi-section
// blocks accumulate with atomicAdd (REDG.F32).

#define BS 128
#define BK 32
#define TCH 32      // max chunks per CTA section (K <= 1024 per section)
#define APAD 40     // bf16 elems per A smem row (32 + 8 pad)
#define BPAD 136    // bf16 elems per B smem row (128 + 8 pad)

#define AHI_OFF 0
#define ALO_OFF (128 * APAD * 2)                 // 10240
#define BHI_OFF (ALO_OFF * 2)                    // 20480
#define BLO_OFF (BHI_OFF + BK * BPAD * 2)        // 29184
#define STAGE_BYTES (BLO_OFF + BK * BPAD * 2)    // 37888
#define NSTAGE 2

#define NMAX 4096ULL
__device__ __align__(16) __nv_bfloat16 gAhi[NMAX * NMAX];
__device__ __align__(16) __nv_bfloat16 gAlo[NMAX * NMAX];
__device__ __align__(16) __nv_bfloat16 gBhi[NMAX * NMAX];
__device__ __align__(16) __nv_bfloat16 gBlo[NMAX * NMAX];

// ---------------- helpers ----------------
__device__ __forceinline__ uint32_t smem_u32(const void* p) {
    uint32_t a;
    asm("{ .reg .u64 t; cvta.to.shared.u64 t, %1; cvt.u32.u64 %0, t; }"
        : "=r"(a) : "l"(p));
    return a;
}
__device__ __forceinline__ uint32_t pack2(float a, float b) {
    __nv_bfloat162 v = __floats2bfloat162_rn(a, b);
    return *reinterpret_cast<uint32_t*>(&v);
}
__device__ __forceinline__ void splitf(float x, float& h, float& l) {
    __nv_bfloat16 bh = __float2bfloat16(x);
    h = __bfloat162float(bh);
    l = x - h;
}
__device__ __forceinline__ void ldsm4(uint32_t* r, uint32_t addr) {
    asm volatile("ldmatrix.sync.aligned.m8n8.x4.shared.b16 {%0,%1,%2,%3}, [%4];"
                 : "=r"(r[0]), "=r"(r[1]), "=r"(r[2]), "=r"(r[3]) : "r"(addr));
}
__device__ __forceinline__ void ldsm4t(uint32_t* r, uint32_t addr) {
    asm volatile("ldmatrix.sync.aligned.m8n8.x4.trans.shared.b16 {%0,%1,%2,%3}, [%4];"
                 : "=r"(r[0]), "=r"(r[1]), "=r"(r[2]), "=r"(r[3]) : "r"(addr));
}
__device__ __forceinline__ void mma16816(float* c, const uint32_t* a, const uint32_t* b) {
    asm volatile(
        "mma.sync.aligned.m16n8k16.row.col.f32.bf16.bf16.f32 "
        "{%0,%1,%2,%3}, {%4,%5,%6,%7}, {%8,%9}, {%0,%1,%2,%3};"
        : "+f"(c[0]), "+f"(c[1]), "+f"(c[2]), "+f"(c[3])
        : "r"(a[0]), "r"(a[1]), "r"(a[2]), "r"(a[3]), "r"(b[0]), "r"(b[1]));
}
__device__ __forceinline__ void cp16(uint32_t dst, const void* src) {
    asm volatile("cp.async.cg.shared.global [%0], [%1], 16;"
                 :: "r"(dst), "l"(__cvta_generic_to_global(src)) : "memory");
}
__device__ __forceinline__ void cp_commit() {
    asm volatile("cp.async.commit_group;" ::: "memory");
}
template<int n> __device__ __forceinline__ void cp_wait() {
    asm volatile("cp.async.wait_group %0;" :: "n"(n) : "memory");
}

// ---------------- zero C ----------------
__global__ __launch_bounds__(256)
void zero_c(float* __restrict__ C, size_t n4)
{
    size_t id = (size_t)blockIdx.x * 256 + threadIdx.x;
    if (id < n4)
        reinterpret_cast<float4*>(C)[id] = make_float4(0.f, 0.f, 0.f, 0.f);
}

// ---------------- prepass: fp32 -> tril-masked bf16 hi/lo ----------------
__global__ __launch_bounds__(256)
void split_prepass(const float* __restrict__ A, const float* __restrict__ B, int N)
{
    size_t per = (size_t)N * N / 8;
    size_t id = (size_t)blockIdx.x * 256 + threadIdx.x;
    if (id >= 2 * per) return;
    const bool isA = id < per;
    size_t e = (isA ? id : id - per) * 8;
    const int row = (int)(e / (size_t)N);
    const int col = (int)(e % (size_t)N);

    const float* S = isA ? A : B;
    __nv_bfloat16* dh = isA ? gAhi : gBhi;
    __nv_bfloat16* dl = isA ? gAlo : gBlo;

    float4 v0 = *reinterpret_cast<const float4*>(S + e);
    float4 v1 = *reinterpret_cast<const float4*>(S + e + 4);
    float f[8] = {v0.x, v0.y, v0.z, v0.w, v1.x, v1.y, v1.z, v1.w};

    uint32_t hp[4], lp[4];
    #pragma unroll
    for (int j = 0; j < 8; j += 2) {
        float x0 = (col + j     > row) ? 0.f : f[j];
        float x1 = (col + j + 1 > row) ? 0.f : f[j + 1];
        float h0, l0, h1, l1;
        splitf(x0, h0, l0);
        splitf(x1, h1, l1);
        hp[j >> 1] = pack2(h0, h1);
        lp[j >> 1] = pack2(l0, l1);
    }
    *reinterpret_cast<uint4*>(dh + e) = make_uint4(hp[0], hp[1], hp[2], hp[3]);
    *reinterpret_cast<uint4*>(dl + e) = make_uint4(lp[0], lp[1], lp[2], lp[3]);
}

// ---------------- main GEMM (split-K sections) ----------------
__global__ __launch_bounds__(256, 2)
void trilmm_mma_kernel(float* __restrict__ C, int N, int nb)
{
    extern __shared__ char smem[];
    const int tid = threadIdx.x;

    // ---- map bid -> (d, bj, sec); d descending so biggest sections start first
    int d, nsec, t = blockIdx.x;
    for (d = nb - 1; d >= 0; d--) {
        nsec = 1 + (d >> 3);                 // ceil(4*(d+1)/TCH) for TCH=32
        int cnt = (nb - d) * nsec;
        if (t < cnt) break;
        t -= cnt;
    }
    const int bj = t / nsec;
    const int sec = t % nsec;
    const int bi = bj + d;

    const int lane = tid & 31;
    const int wid  = tid >> 5;
    const int wm   = wid >> 2;
    const int wn   = wid & 3;

    const int row0 = bi * BS, col0 = bj * BS;
    const int nchunkTot = (d + 1) * (BS / BK);
    const int cBeg = sec * TCH;
    const int nchunk = min(TCH, nchunkTot - cBeg);
    const int kBeg = bj * BS + cBeg * BK;

    const uint32_t sb = smem_u32(smem);

    float acc[4][4][4];
    #pragma unroll
    for (int i = 0; i < 4; i++)
        #pragma unroll
        for (int j = 0; j < 4; j++)
            #pragma unroll
            for (int e = 0; e < 4; e++)
                acc[i][j][e] = 0.f;

    uint32_t a_off[4];
    #pragma unroll
    for (int mt = 0; mt < 4; mt++)
        a_off[mt] = (uint32_t)(((wm * 64 + mt * 16 + (lane & 15)) * APAD
                                + (lane >> 4) * 8) * 2);
    uint32_t b_off[2];
    #pragma unroll
    for (int p = 0; p < 2; p++)
        b_off[p] = (uint32_t)(((lane & 15) * BPAD
                               + wn * 32 + p * 16 + (lane >> 4) * 8) * 2);

    const int aRow = tid >> 2, aSeg = (tid & 3) * 8;
    const int bRow = tid >> 4, bSeg = (tid & 15) * 8;

    auto issue = [&](int c) {
        const uint32_t base = sb + (uint32_t)(c % NSTAGE) * STAGE_BYTES;
        const int k0 = kBeg + c * BK;
        #pragma unroll
        for (int i = 0; i < 2; i++) {
            const int r = aRow + i * 64;
            const size_t g = (size_t)(row0 + r) * N + k0 + aSeg;
            const uint32_t dst = base + AHI_OFF + (uint32_t)((r * APAD + aSeg) * 2);
            cp16(dst, gAhi + g);
            cp16(dst + (ALO_OFF - AHI_OFF), gAlo + g);
        }
        #pragma unroll
        for (int i = 0; i < 2; i++) {
            const int r = bRow + i * 16;
            const size_t g = (size_t)(k0 + r) * N + col0 + bSeg;
            const uint32_t dst = base + BHI_OFF + (uint32_t)((r * BPAD + bSeg) * 2);
            cp16(dst, gBhi + g);
            cp16(dst + (BLO_OFF - BHI_OFF), gBlo + g);
        }
        cp_commit();
    };

    issue(0);

    for (int c = 0; c < nchunk; c++) {
        if (c + 1 < nchunk) {
            issue(c + 1);
            cp_wait<1>();
        } else {
            cp_wait<0>();
        }
        __syncthreads();

        const uint32_t stB = sb + (uint32_t)(c % NSTAGE) * STAGE_BYTES;
        const uint32_t aHiB = stB + AHI_OFF, aLoB = stB + ALO_OFF;
        const uint32_t bHiB = stB + BHI_OFF, bLoB = stB + BLO_OFF;

        #pragma unroll
        for (int ks = 0; ks < 2; ks++) {
            uint32_t af[4][4], bh[2][4], bl[2][4];
            #pragma unroll
            for (int mt = 0; mt < 4; mt++)
                ldsm4(af[mt], aHiB + a_off[mt] + ks * 32);
            #pragma unroll
            for (int p = 0; p < 2; p++) {
                ldsm4t(bh[p], bHiB + b_off[p] + ks * (16 * BPAD * 2));
                ldsm4t(bl[p], bLoB + b_off[p] + ks * (16 * BPAD * 2));
            }
            #pragma unroll
            for (int mt = 0; mt < 4; mt++)
                #pragma unroll
                for (int nt = 0; nt < 4; nt++)
                    mma16816(acc[mt][nt], af[mt], &bh[nt >> 1][(nt & 1) * 2]);
            #pragma unroll
            for (int mt = 0; mt < 4; mt++)
                #pragma unroll
                for (int nt = 0; nt < 4; nt++)
                    mma16816(acc[mt][nt], af[mt], &bl[nt >> 1][(nt & 1) * 2]);
            #pragma unroll
            for (int mt = 0; mt < 4; mt++)
                ldsm4(af[mt], aLoB + a_off[mt] + ks * 32);
            #pragma unroll
            for (int mt = 0; mt < 4; mt++)
                #pragma unroll
                for (int nt = 0; nt < 4; nt++)
                    mma16816(acc[mt][nt], af[mt], &bh[nt >> 1][(nt & 1) * 2]);
        }

        __syncthreads();
    }

    // ---- epilogue ----
    if (nsec == 1) {
        // only CTA writing this block: plain stores over the zeroed C
        #pragma unroll
        for (int mt = 0; mt < 4; mt++) {
            #pragma unroll
            for (int nt = 0; nt < 4; nt++) {
                const int r  = row0 + wm * 64 + mt * 16 + (lane >> 2);
                const int cb = col0 + wn * 32 + nt * 8 + (lane & 3) * 2;
                float2 v0 = make_float2(acc[mt][nt][0], acc[mt][nt][1]);
                float2 v1 = make_float2(acc[mt][nt][2], acc[mt][nt][3]);
                *reinterpret_cast<float2*>(&C[(size_t)r * N + cb])       = v0;
                *reinterpret_cast<float2*>(&C[(size_t)(r + 8) * N + cb]) = v1;
            }
        }
    } else {
        // multiple K-sections accumulate into this block
        #pragma unroll
        for (int mt = 0; mt < 4; mt++) {
            #pragma unroll
            for (int nt = 0; nt < 4; nt++) {
                const int r  = row0 + wm * 64 + mt * 16 + (lane >> 2);
                const int cb = col0 + wn * 32 + nt * 8 + (lane & 3) * 2;
                atomicAdd(&C[(size_t)r * N + cb],           acc[mt][nt][0]);
                atomicAdd(&C[(size_t)r * N + cb + 1],       acc[mt][nt][1]);
                atomicAdd(&C[(size_t)(r + 8) * N + cb],     acc[mt][nt][2]);
                atomicAdd(&C[(size_t)(r + 8) * N + cb + 1], acc[mt][nt][3]);
            }
        }
    }
}

// ---------------- launch ----------------
extern "C" void kernel_launch(void* const* d_in, const int* in_sizes, int n_in,
                              void* d_out, int out_size)
{
    const float* A = (const float*)d_in[0];
    const float* B = (const float*)d_in[1];
    float* C = (float*)d_out;

    int N = 1;
    {
        long long total = in_sizes[0];
        int lo = 1, hi = 65536;
        while (lo < hi) {
            int mid = (lo + hi) >> 1;
            if ((long long)mid * mid < total) lo = mid + 1; else hi = mid;
        }
        N = lo;
    }
    const int nb = N / BS;

    // zero C (covers upper triangle too; no zero-fill CTAs in main kernel)
    {
        size_t n4 = (size_t)N * N / 4;
        zero_c<<<(int)((n4 + 255) / 256), 256>>>(C, n4);
    }

    // prepass
    {
        long long groups = 2LL * N * N / 8;
        split_prepass<<<(int)((groups + 255) / 256), 256>>>(A, B, N);
    }

    // total split-K sections
    int grid = 0;
    for (int d = 0; d < nb; d++)
        grid += (nb - d) * (1 + (d >> 3));

    cudaFuncSetAttribute(trilmm_mma_kernel,
                         cudaFuncAttributeMaxDynamicSharedMemorySize,
                         STAGE_BYTES * NSTAGE);
    trilmm_mma_kernel<<<grid, 256, STAGE_BYTES * NSTAGE>>>(C, N, nb);
}

// round 10
// speedup vs baseline: 3.6244x; 1.0236x over previous
#include <cuda_runtime.h>
#include <cuda_bf16.h>
#include <stdint.h>

// C = tril(tril(A) @ tril(B)), N=4096 fp32.
// R10: fused zero+prepass -> bf16 hi/lo planes; split-K (TCH=16) balanced GEMM,
// 3-stage cp.async pipeline (one barrier/chunk), mma.sync m16n8k16 3-pass bf16.

#define BS 128
#define BK 32
#define TCH 16      // max chunks per CTA section (K <= 512 per section)
#define APAD 40     // bf16 elems per A smem row (32 + 8 pad)
#define BPAD 136    // bf16 elems per B smem row (128 + 8 pad)

#define AHI_OFF 0
#define ALO_OFF (128 * APAD * 2)                 // 10240
#define BHI_OFF (ALO_OFF * 2)                    // 20480
#define BLO_OFF (BHI_OFF + BK * BPAD * 2)        // 29184
#define STAGE_BYTES (BLO_OFF + BK * BPAD * 2)    // 37888
#define NSTAGE 3                                 // 113664 B dynamic smem

#define NMAX 4096ULL
__device__ __align__(16) __nv_bfloat16 gAhi[NMAX * NMAX];
__device__ __align__(16) __nv_bfloat16 gAlo[NMAX * NMAX];
__device__ __align__(16) __nv_bfloat16 gBhi[NMAX * NMAX];
__device__ __align__(16) __nv_bfloat16 gBlo[NMAX * NMAX];

// ---------------- helpers ----------------
__device__ __forceinline__ uint32_t smem_u32(const void* p) {
    uint32_t a;
    asm("{ .reg .u64 t; cvta.to.shared.u64 t, %1; cvt.u32.u64 %0, t; }"
        : "=r"(a) : "l"(p));
    return a;
}
__device__ __forceinline__ uint32_t pack2(float a, float b) {
    __nv_bfloat162 v = __floats2bfloat162_rn(a, b);
    return *reinterpret_cast<uint32_t*>(&v);
}
__device__ __forceinline__ void splitf(float x, float& h, float& l) {
    __nv_bfloat16 bh = __float2bfloat16(x);
    h = __bfloat162float(bh);
    l = x - h;
}
__device__ __forceinline__ void ldsm4(uint32_t* r, uint32_t addr) {
    asm volatile("ldmatrix.sync.aligned.m8n8.x4.shared.b16 {%0,%1,%2,%3}, [%4];"
                 : "=r"(r[0]), "=r"(r[1]), "=r"(r[2]), "=r"(r[3]) : "r"(addr));
}
__device__ __forceinline__ void ldsm4t(uint32_t* r, uint32_t addr) {
    asm volatile("ldmatrix.sync.aligned.m8n8.x4.trans.shared.b16 {%0,%1,%2,%3}, [%4];"
                 : "=r"(r[0]), "=r"(r[1]), "=r"(r[2]), "=r"(r[3]) : "r"(addr));
}
__device__ __forceinline__ void mma16816(float* c, const uint32_t* a, const uint32_t* b) {
    asm volatile(
        "mma.sync.aligned.m16n8k16.row.col.f32.bf16.bf16.f32 "
        "{%0,%1,%2,%3}, {%4,%5,%6,%7}, {%8,%9}, {%0,%1,%2,%3};"
        : "+f"(c[0]), "+f"(c[1]), "+f"(c[2]), "+f"(c[3])
        : "r"(a[0]), "r"(a[1]), "r"(a[2]), "r"(a[3]), "r"(b[0]), "r"(b[1]));
}
__device__ __forceinline__ void cp16(uint32_t dst, const void* src) {
    asm volatile("cp.async.cg.shared.global [%0], [%1], 16;"
                 :: "r"(dst), "l"(__cvta_generic_to_global(src)) : "memory");
}
__device__ __forceinline__ void cp_commit() {
    asm volatile("cp.async.commit_group;" ::: "memory");
}
template<int n> __device__ __forceinline__ void cp_wait() {
    asm volatile("cp.async.wait_group %0;" :: "n"(n) : "memory");
}

// ------- fused: zero C  +  fp32 -> tril-masked bf16 hi/lo planes -------
__global__ __launch_bounds__(256)
void prepass_fused(const float* __restrict__ A, const float* __restrict__ B,
                   float* __restrict__ C, int N)
{
    const size_t per = (size_t)N * N / 8;       // 8-elem groups per matrix
    const size_t zgrp = (size_t)N * N / 4;      // float4 groups in C
    size_t id = (size_t)blockIdx.x * 256 + threadIdx.x;

    if (id >= 2 * per) {
        size_t z = id - 2 * per;
        if (z < zgrp)
            reinterpret_cast<float4*>(C)[z] = make_float4(0.f, 0.f, 0.f, 0.f);
        return;
    }

    const bool isA = id < per;
    size_t e = (isA ? id : id - per) * 8;
    const int row = (int)(e / (size_t)N);
    const int col = (int)(e % (size_t)N);

    const float* S = isA ? A : B;
    __nv_bfloat16* dh = isA ? gAhi : gBhi;
    __nv_bfloat16* dl = isA ? gAlo : gBlo;

    float4 v0 = *reinterpret_cast<const float4*>(S + e);
    float4 v1 = *reinterpret_cast<const float4*>(S + e + 4);
    float f[8] = {v0.x, v0.y, v0.z, v0.w, v1.x, v1.y, v1.z, v1.w};

    uint32_t hp[4], lp[4];
    #pragma unroll
    for (int j = 0; j < 8; j += 2) {
        // tril mask: A(i,k): k<=i ; B(k,n): n<=k  =>  col <= row for both
        float x0 = (col + j     > row) ? 0.f : f[j];
        float x1 = (col + j + 1 > row) ? 0.f : f[j + 1];
        float h0, l0, h1, l1;
        splitf(x0, h0, l0);
        splitf(x1, h1, l1);
        hp[j >> 1] = pack2(h0, h1);
        lp[j >> 1] = pack2(l0, l1);
    }
    *reinterpret_cast<uint4*>(dh + e) = make_uint4(hp[0], hp[1], hp[2], hp[3]);
    *reinterpret_cast<uint4*>(dl + e) = make_uint4(lp[0], lp[1], lp[2], lp[3]);
}

// ---------------- main GEMM (split-K sections, 3-stage pipeline) ----------------
__global__ __launch_bounds__(256, 2)
void trilmm_mma_kernel(float* __restrict__ C, int N, int nb)
{
    extern __shared__ char smem[];
    const int tid = threadIdx.x;

    // map bid -> (d, bj, sec); d descending (largest sections first)
    int d, nsec, t = blockIdx.x;
    for (d = nb - 1; d >= 0; d--) {
        nsec = 1 + (d >> 2);                  // ceil(4*(d+1)/TCH), TCH=16
        int cnt = (nb - d) * nsec;
        if (t < cnt) break;
        t -= cnt;
    }
    const int bj = t / nsec;
    const int sec = t % nsec;
    const int bi = bj + d;

    const int lane = tid & 31;
    const int wid  = tid >> 5;
    const int wm   = wid >> 2;
    const int wn   = wid & 3;

    const int row0 = bi * BS, col0 = bj * BS;
    const int nchunkTot = (d + 1) * (BS / BK);
    const int cBeg = sec * TCH;
    const int nchunk = min(TCH, nchunkTot - cBeg);
    const int kBeg = bj * BS + cBeg * BK;

    const uint32_t sb = smem_u32(smem);

    float acc[4][4][4];
    #pragma unroll
    for (int i = 0; i < 4; i++)
        #pragma unroll
        for (int j = 0; j < 4; j++)
            #pragma unroll
            for (int e = 0; e < 4; e++)
                acc[i][j][e] = 0.f;

    uint32_t a_off[4];
    #pragma unroll
    for (int mt = 0; mt < 4; mt++)
        a_off[mt] = (uint32_t)(((wm * 64 + mt * 16 + (lane & 15)) * APAD
                                + (lane >> 4) * 8) * 2);
    uint32_t b_off[2];
    #pragma unroll
    for (int p = 0; p < 2; p++)
        b_off[p] = (uint32_t)(((lane & 15) * BPAD
                               + wn * 32 + p * 16 + (lane >> 4) * 8) * 2);

    const int aRow = tid >> 2, aSeg = (tid & 3) * 8;
    const int bRow = tid >> 4, bSeg = (tid & 15) * 8;

    auto issue = [&](int c) {
        const uint32_t base = sb + (uint32_t)(c % NSTAGE) * STAGE_BYTES;
        const int k0 = kBeg + c * BK;
        #pragma unroll
        for (int i = 0; i < 2; i++) {
            const int r = aRow + i * 64;
            const size_t g = (size_t)(row0 + r) * N + k0 + aSeg;
            const uint32_t dst = base + AHI_OFF + (uint32_t)((r * APAD + aSeg) * 2);
            cp16(dst, gAhi + g);
            cp16(dst + (ALO_OFF - AHI_OFF), gAlo + g);
        }
        #pragma unroll
        for (int i = 0; i < 2; i++) {
            const int r = bRow + i * 16;
            const size_t g = (size_t)(k0 + r) * N + col0 + bSeg;
            const uint32_t dst = base + BHI_OFF + (uint32_t)((r * BPAD + bSeg) * 2);
            cp16(dst, gBhi + g);
            cp16(dst + (BLO_OFF - BHI_OFF), gBlo + g);
        }
        cp_commit();
    };

    // prologue: two stages in flight
    issue(0);
    if (nchunk > 1) issue(1);

    for (int c = 0; c < nchunk; c++) {
        // wait for stage c (leave stage c+1 in flight), single barrier per chunk
        if (c + 1 < nchunk) cp_wait<1>(); else cp_wait<0>();
        __syncthreads();

        // refill pipeline: buffer (c+2)%3 was last read at chunk c-1 (done by barrier)
        if (c + 2 < nchunk) issue(c + 2);

        const uint32_t stB = sb + (uint32_t)(c % NSTAGE) * STAGE_BYTES;
        const uint32_t aHiB = stB + AHI_OFF, aLoB = stB + ALO_OFF;
        const uint32_t bHiB = stB + BHI_OFF, bLoB = stB + BLO_OFF;

        #pragma unroll
        for (int ks = 0; ks < 2; ks++) {
            uint32_t af[4][4], bh[2][4], bl[2][4];
            #pragma unroll
            for (int mt = 0; mt < 4; mt++)
                ldsm4(af[mt], aHiB + a_off[mt] + ks * 32);
            #pragma unroll
            for (int p = 0; p < 2; p++) {
                ldsm4t(bh[p], bHiB + b_off[p] + ks * (16 * BPAD * 2));
                ldsm4t(bl[p], bLoB + b_off[p] + ks * (16 * BPAD * 2));
            }
            #pragma unroll
            for (int mt = 0; mt < 4; mt++)
                #pragma unroll
                for (int nt = 0; nt < 4; nt++)
                    mma16816(acc[mt][nt], af[mt], &bh[nt >> 1][(nt & 1) * 2]);
            #pragma unroll
            for (int mt = 0; mt < 4; mt++)
                #pragma unroll
                for (int nt = 0; nt < 4; nt++)
                    mma16816(acc[mt][nt], af[mt], &bl[nt >> 1][(nt & 1) * 2]);
            #pragma unroll
            for (int mt = 0; mt < 4; mt++)
                ldsm4(af[mt], aLoB + a_off[mt] + ks * 32);
            #pragma unroll
            for (int mt = 0; mt < 4; mt++)
                #pragma unroll
                for (int nt = 0; nt < 4; nt++)
                    mma16816(acc[mt][nt], af[mt], &bh[nt >> 1][(nt & 1) * 2]);
        }
        // no trailing barrier: next iteration's top barrier orders reuse
    }

    // ---- epilogue ----
    if (nsec == 1) {
        #pragma unroll
        for (int mt = 0; mt < 4; mt++) {
            #pragma unroll
            for (int nt = 0; nt < 4; nt++) {
                const int r  = row0 + wm * 64 + mt * 16 + (lane >> 2);
                const int cb = col0 + wn * 32 + nt * 8 + (lane & 3) * 2;
                float2 v0 = make_float2(acc[mt][nt][0], acc[mt][nt][1]);
                float2 v1 = make_float2(acc[mt][nt][2], acc[mt][nt][3]);
                *reinterpret_cast<float2*>(&C[(size_t)r * N + cb])       = v0;
                *reinterpret_cast<float2*>(&C[(size_t)(r + 8) * N + cb]) = v1;
            }
        }
    } else {
        #pragma unroll
        for (int mt = 0; mt < 4; mt++) {
            #pragma unroll
            for (int nt = 0; nt < 4; nt++) {
                const int r  = row0 + wm * 64 + mt * 16 + (lane >> 2);
                const int cb = col0 + wn * 32 + nt * 8 + (lane & 3) * 2;
                atomicAdd(&C[(size_t)r * N + cb],           acc[mt][nt][0]);
                atomicAdd(&C[(size_t)r * N + cb + 1],       acc[mt][nt][1]);
                atomicAdd(&C[(size_t)(r + 8) * N + cb],     acc[mt][nt][2]);
                atomicAdd(&C[(size_t)(r + 8) * N + cb + 1], acc[mt][nt][3]);
            }
        }
    }
}

// ---------------- launch ----------------
extern "C" void kernel_launch(void* const* d_in, const int* in_sizes, int n_in,
                              void* d_out, int out_size)
{
    const float* A = (const float*)d_in[0];
    const float* B = (const float*)d_in[1];
    float* C = (float*)d_out;

    int N = 1;
    {
        long long total = in_sizes[0];
        int lo = 1, hi = 65536;
        while (lo < hi) {
            int mid = (lo + hi) >> 1;
            if ((long long)mid * mid < total) lo = mid + 1; else hi = mid;
        }
        N = lo;
    }
    const int nb = N / BS;

    // fused zero + split prepass
    {
        long long work = 2LL * N * N / 8 + (long long)N * N / 4;
        prepass_fused<<<(int)((work + 255) / 256), 256>>>(A, B, C, N);
    }

    // total split-K sections (TCH=16)
    int grid = 0;
    for (int d = 0; d < nb; d++)
        grid += (nb - d) * (1 + (d >> 2));

    cudaFuncSetAttribute(trilmm_mma_kernel,
                         cudaFuncAttributeMaxDynamicSharedMemorySize,
                         STAGE_BYTES * NSTAGE);
    trilmm_mma_kernel<<<grid, 256, STAGE_BYTES * NSTAGE>>>(C, N, nb);
}